// round 2
// baseline (speedup 1.0000x reference)
#include <cuda_runtime.h>
#include <math.h>
#include <float.h>
#include <stdint.h>

// ============================================================================
// KNN classifier:
//   sim = Q[2048,1024] @ T[100000,1024]^T          (fp32 SIMT GEMM, pass 1)
//   per-row top-200 -> softmax(T=0.07) -> 4 class histograms (pass 2, fused)
//
// R1 baseline: FP32 end-to-end (precision analysis: softmax at T=0.07 needs
// |err(sim)| << 0.07 absolute; fp32 accumulation gives ~1e-4).
// Roadmap: bf16 tcgen05 prefilter + exact fp32 rescore of ~256 cand/row.
// ============================================================================

#define NQ    2048
#define NT    100000
#define DIM   1024
#define NCLS  1000
#define MAXK  200
#define TINV  (1.0f / 0.07f)

// 819.2 MB scratch for the similarity matrix (zero-init BSS, allowed scratch).
__device__ float g_sim[(size_t)NQ * NT];

// ---------------------------------------------------------------------------
// Pass 1: fp32 GEMM, C[m,n] = sum_k A[m,k]*B[n,k]   (both K-major => "NT")
// 128x128 tile, BK=16, 256 threads, 8x8 register tile per thread.
// ---------------------------------------------------------------------------
#define BM 128
#define BN 128
#define BK 16
#define TM 8
#define TN 8

__global__ void __launch_bounds__(256, 2)
gemm_f32(const float* __restrict__ A, const float* __restrict__ B)
{
    __shared__ float As[BK][BM];
    __shared__ float Bs[BK][BN];

    const int tid = threadIdx.x;
    const int bm  = blockIdx.y * BM;
    const int bn  = blockIdx.x * BN;

    const int tm = (tid >> 4) * TM;      // 0..120 step 8
    const int tn = (tid & 15) * TN;      // 0..120 step 8

    // loader decomposition: 128 rows x 16 k per tile; float4 along K
    const int lr = tid >> 2;             // 0..63
    const int lk = (tid & 3) * 4;        // 0,4,8,12

    float acc[TM][TN];
    #pragma unroll
    for (int i = 0; i < TM; i++)
        #pragma unroll
        for (int j = 0; j < TN; j++) acc[i][j] = 0.f;

    for (int k0 = 0; k0 < DIM; k0 += BK) {
        #pragma unroll
        for (int h = 0; h < 2; h++) {
            const int r = lr + h * 64;
            // A tile load (always in-bounds: NQ % BM == 0)
            float4 va = *(const float4*)(A + (size_t)(bm + r) * DIM + k0 + lk);
            As[lk + 0][r] = va.x; As[lk + 1][r] = va.y;
            As[lk + 2][r] = va.z; As[lk + 3][r] = va.w;
            // B tile load (guard: last N tile is partial, 100000 % 128 == 32)
            const int n = bn + r;
            float4 vb = make_float4(0.f, 0.f, 0.f, 0.f);
            if (n < NT) vb = *(const float4*)(B + (size_t)n * DIM + k0 + lk);
            Bs[lk + 0][r] = vb.x; Bs[lk + 1][r] = vb.y;
            Bs[lk + 2][r] = vb.z; Bs[lk + 3][r] = vb.w;
        }
        __syncthreads();

        #pragma unroll
        for (int k = 0; k < BK; k++) {
            float a[TM], b[TN];
            *(float4*)&a[0] = *(const float4*)&As[k][tm];
            *(float4*)&a[4] = *(const float4*)&As[k][tm + 4];
            *(float4*)&b[0] = *(const float4*)&Bs[k][tn];
            *(float4*)&b[4] = *(const float4*)&Bs[k][tn + 4];
            #pragma unroll
            for (int i = 0; i < TM; i++)
                #pragma unroll
                for (int j = 0; j < TN; j++)
                    acc[i][j] = fmaf(a[i], b[j], acc[i][j]);
        }
        __syncthreads();
    }

    #pragma unroll
    for (int i = 0; i < TM; i++) {
        float* crow = g_sim + (size_t)(bm + tm + i) * NT;
        #pragma unroll
        for (int j = 0; j < TN; j++) {
            const int n = bn + tn + j;
            if (n < NT) crow[n] = acc[i][j];
        }
    }
}

// ---------------------------------------------------------------------------
// Pass 2: per-row (one block per row):
//   shared histogram -> rank-200 threshold bin -> collect candidates ->
//   bitonic sort (value desc, index asc — matches jax.lax.top_k) ->
//   softmax over 200 -> 4 prefix class-histograms.
// ---------------------------------------------------------------------------
#define NBINS 4096
#define HLO   (-256.0f)
#define HSC   8.0f          // bins per unit sim; covers [-256, 256)
#define CAND  512
#define NTHR  256

__device__ __forceinline__ int bin_of(float v)
{
    int b = (int)((v - HLO) * HSC);
    return min(max(b, 0), NBINS - 1);
}

__global__ void __launch_bounds__(NTHR)
topk_kernel(const int* __restrict__ labels, float* __restrict__ out)
{
    const int row = blockIdx.x;
    const float* __restrict__ sim = g_sim + (size_t)row * NT;
    const int tid = threadIdx.x;

    __shared__ unsigned hist[NBINS];
    __shared__ unsigned long long ckey[CAND];
    __shared__ int   s_cnt, s_bstar;
    __shared__ float s_red[NTHR];
    __shared__ float prob[NCLS];
    __shared__ float wgt[MAXK];
    __shared__ int   lab[MAXK];

    for (int b = tid; b < NBINS; b += NTHR) hist[b] = 0;
    if (tid == 0) s_cnt = 0;
    __syncthreads();

    // Phase 1: value histogram
    for (int i = tid; i < NT; i += NTHR)
        atomicAdd(&hist[bin_of(sim[i])], 1u);
    __syncthreads();

    // Phase 2: scan from the top for the rank-200 bin
    if (tid == 0) {
        unsigned cum = 0;
        int b = NBINS - 1;
        while (b >= 0) {
            cum += hist[b];
            if (cum >= MAXK) break;
            b--;
        }
        s_bstar = (b < 0) ? 0 : b;
    }
    __syncthreads();
    const int bstar = s_bstar;

    // Phase 3: collect candidates (identical bin predicate => exact count match)
    for (int i = tid; i < NT; i += NTHR) {
        const float v = sim[i];
        if (bin_of(v) >= bstar) {
            const int p = atomicAdd(&s_cnt, 1);
            if (p < CAND) {
                unsigned u = __float_as_uint(v);
                unsigned s = (u & 0x80000000u) ? ~u : (u | 0x80000000u);
                // value desc primary, index asc secondary (ties): ~i is larger
                // for smaller i, so a plain descending u64 sort reproduces
                // jax.lax.top_k ordering.
                ckey[p] = ((unsigned long long)s << 32) | (unsigned)(~(unsigned)i);
            }
        }
    }
    __syncthreads();
    const int cnt = min(s_cnt, CAND);
    for (int i = tid; i < CAND; i += NTHR)
        if (i >= cnt) ckey[i] = 0ull;           // pads sort last (== -inf)
    __syncthreads();

    // Phase 4: bitonic sort, descending, 512 elems / 256 threads
    for (int ksz = 2; ksz <= CAND; ksz <<= 1) {
        for (int st = ksz >> 1; st > 0; st >>= 1) {
            for (int j = tid; j < CAND; j += NTHR) {
                const int ixj = j ^ st;
                if (ixj > j) {
                    const unsigned long long a = ckey[j], b = ckey[ixj];
                    const bool descBlock = ((j & ksz) == 0);
                    if (descBlock ? (a < b) : (a > b)) {
                        ckey[j] = b; ckey[ixj] = a;
                    }
                }
            }
            __syncthreads();
        }
    }

    // Phase 5: softmax weights over top-200 (MAXK < NTHR: one elem per thread)
    float maxv;
    {
        const unsigned s0 = (unsigned)(ckey[0] >> 32);
        const unsigned u0 = (s0 & 0x80000000u) ? (s0 & 0x7fffffffu) : ~s0;
        maxv = __uint_as_float(u0);
    }
    float wv = 0.f;
    if (tid < MAXK) {
        const unsigned long long k = ckey[tid];
        const unsigned s = (unsigned)(k >> 32);
        const unsigned u = (s & 0x80000000u) ? (s & 0x7fffffffu) : ~s;
        const float v = __uint_as_float(u);
        const int idx = (int)(~(unsigned)k);
        wv = expf((v - maxv) * TINV);
        wgt[tid] = wv;
        lab[tid] = labels[idx];
    }
    s_red[tid] = wv;
    __syncthreads();
    for (int off = NTHR / 2; off > 0; off >>= 1) {
        if (tid < off) s_red[tid] += s_red[tid + off];
        __syncthreads();
    }
    const float inv = 1.0f / s_red[0];

    // Phase 6: 4 prefix class-histograms (k = 10, 20, 100, 200)
    const int KS[4] = {10, 20, 100, 200};
    #pragma unroll
    for (int kk = 0; kk < 4; kk++) {
        for (int c = tid; c < NCLS; c += NTHR) prob[c] = 0.f;
        __syncthreads();
        if (tid < KS[kk]) atomicAdd(&prob[lab[tid]], wgt[tid] * inv);
        __syncthreads();
        float* o = out + ((size_t)kk * NQ + row) * NCLS;
        for (int c = tid; c < NCLS; c += NTHR) o[c] = prob[c];
        __syncthreads();
    }
}

// ---------------------------------------------------------------------------
extern "C" void kernel_launch(void* const* d_in, const int* in_sizes, int n_in,
                              void* d_out, int out_size)
{
    const float* A      = (const float*)d_in[0];   // features_rank  [2048,1024]
    const float* B      = (const float*)d_in[1];   // train_features [100000,1024]
    const int*   labels = (const int*)d_in[2];     // train_labels   [100000]
    float*       out    = (float*)d_out;           // 4 x [2048,1000] fp32

    dim3 grid((NT + BN - 1) / BN, NQ / BM);        // 782 x 16
    gemm_f32<<<grid, 256>>>(A, B);
    topk_kernel<<<NQ, NTHR>>>(labels, out);
}

// round 6
// speedup vs baseline: 7.0701x; 7.0701x over previous
#include <cuda_runtime.h>
#include <cuda_bf16.h>
#include <math.h>
#include <float.h>
#include <stdint.h>

// ============================================================================
// KNN classifier, R6 (= R5 resubmit; R5 failed on harness device-init infra
// flake, not kernel): bf16 mma.sync (HMMA) prefilter GEMM + exact fp32 rescore.
// (tcgen05 is unusable: harness compiles at compute_103, not compute_103a.)
//   1) convert A,B fp32 -> bf16
//   2) sim_approx = bf16 GEMM via mma.sync.m16n8k16 + ldmatrix + cp.async
//   3) per row: histogram -> rank-200 bin -> candidates (margin 1.0) ->
//      exact fp32 rescore -> top-200 sort -> softmax(T=.07) -> 4 histograms
// ============================================================================

#define NQ    2048
#define NT    100000
#define DIM   1024
#define NCLS  1000
#define MAXK  200
#define TINV  (1.0f / 0.07f)

__device__ __nv_bfloat16 g_simh[(size_t)NQ * NT];     // 409.6 MB approx sims
__device__ __nv_bfloat16 g_bA[(size_t)NQ * DIM];      // 4 MB
__device__ __nv_bfloat16 g_bB[(size_t)NT * DIM];      // 204.8 MB

__device__ __forceinline__ uint32_t smem_u32(const void* p) {
    uint32_t a;
    asm("{ .reg .u64 t; cvta.to.shared.u64 t, %1; cvt.u32.u64 %0, t; }"
        : "=r"(a) : "l"(p));
    return a;
}
#define CP_ASYNC16(dst, src) \
    asm volatile("cp.async.ca.shared.global [%0], [%1], 16;" \
                 :: "r"(dst), "l"(src) : "memory")
#define CP_ASYNC16_Z(dst, src, sz) \
    asm volatile("cp.async.ca.shared.global [%0], [%1], 16, %2;" \
                 :: "r"(dst), "l"(src), "r"(sz) : "memory")
#define CP_COMMIT() asm volatile("cp.async.commit_group;" ::: "memory")
#define CP_WAIT(n)  asm volatile("cp.async.wait_group %0;" :: "n"(n) : "memory")

// ---------------------------------------------------------------------------
// fp32 -> bf16 converter (8 elems/thread)
// ---------------------------------------------------------------------------
__global__ void conv_bf16(const float* __restrict__ src,
                          __nv_bfloat16* __restrict__ dst, int n8)
{
    int i = blockIdx.x * 256 + threadIdx.x;
    if (i >= n8) return;
    const float4* s = (const float4*)src;
    float4 v0 = s[2 * i], v1 = s[2 * i + 1];
    __nv_bfloat162 h0 = __float22bfloat162_rn(make_float2(v0.x, v0.y));
    __nv_bfloat162 h1 = __float22bfloat162_rn(make_float2(v0.z, v0.w));
    __nv_bfloat162 h2 = __float22bfloat162_rn(make_float2(v1.x, v1.y));
    __nv_bfloat162 h3 = __float22bfloat162_rn(make_float2(v1.z, v1.w));
    uint4 o;
    o.x = *(uint32_t*)&h0; o.y = *(uint32_t*)&h1;
    o.z = *(uint32_t*)&h2; o.w = *(uint32_t*)&h3;
    ((uint4*)dst)[i] = o;
}

// ---------------------------------------------------------------------------
// bf16 GEMM: C[m,n] = sum_k A[m,k]B[n,k] via mma.sync m16n8k16 (row.col).
// 128x128 tile, BK=32, 256 thr = 8 warps (2M x 4N), warp tile 64x32.
// Double-buffered cp.async; padded SMEM stride (40 bf16) => ldmatrix
// conflict-free (row stride 20 banks, 8-row starts all distinct mod 32).
// ---------------------------------------------------------------------------
#define BM 128
#define BN 128
#define BK 32
#define KPAD 40
#define NCHK (DIM / BK)        // 32

__global__ void __launch_bounds__(256)
gemm_mma(const __nv_bfloat16* __restrict__ Ab, const __nv_bfloat16* __restrict__ Bb)
{
    __shared__ __nv_bfloat16 As[2][BM * KPAD];
    __shared__ __nv_bfloat16 Bs[2][BN * KPAD];

    const int tid  = threadIdx.x;
    const int lane = tid & 31;
    const int wid  = tid >> 5;
    const int wm   = wid & 1;          // 0..1  (64-row block)
    const int wn   = wid >> 1;         // 0..3  (32-col block)
    const int m0   = blockIdx.x * BM;
    const int n0   = blockIdx.y * BN;

    const uint32_t sA[2] = { smem_u32(&As[0][0]), smem_u32(&As[1][0]) };
    const uint32_t sB[2] = { smem_u32(&Bs[0][0]), smem_u32(&Bs[1][0]) };

    float acc[4][4][4];
    #pragma unroll
    for (int i = 0; i < 4; i++)
        #pragma unroll
        for (int j = 0; j < 4; j++)
            #pragma unroll
            for (int q = 0; q < 4; q++) acc[i][j][q] = 0.f;

    // tile loader: 512 16B-chunks each for A and B; 2 per thread per matrix
    auto load_tile = [&](int buf, int k0) {
        #pragma unroll
        for (int p = 0; p < 2; p++) {
            const int cid = tid + p * 256;
            const int r = cid >> 2, cc = cid & 3;
            const uint32_t da = sA[buf] + (uint32_t)(r * KPAD + cc * 8) * 2;
            CP_ASYNC16(da, Ab + (size_t)(m0 + r) * DIM + k0 + cc * 8);
            const int n = n0 + r;
            const int ncl = n < NT ? n : NT - 1;
            const uint32_t db = sB[buf] + (uint32_t)(r * KPAD + cc * 8) * 2;
            CP_ASYNC16_Z(db, Bb + (size_t)ncl * DIM + k0 + cc * 8,
                         n < NT ? 16u : 0u);
        }
    };

    load_tile(0, 0);
    CP_COMMIT();

    for (int kc = 0; kc < NCHK; kc++) {
        const int buf = kc & 1;
        __syncthreads();                     // other buffer free for reload
        if (kc + 1 < NCHK) {
            load_tile(buf ^ 1, (kc + 1) * BK);
            CP_COMMIT();
            CP_WAIT(1);                      // tile kc landed; kc+1 in flight
        } else {
            CP_WAIT(0);
        }
        __syncthreads();                     // tile kc visible to all

        #pragma unroll
        for (int ks = 0; ks < 2; ks++) {     // two k16 steps per BK=32
            uint32_t a[4][4];
            #pragma unroll
            for (int mf = 0; mf < 4; mf++) {
                const int row = wm * 64 + mf * 16 + (lane & 15);
                const int col = ks * 16 + (lane >> 4) * 8;
                const uint32_t addr = sA[buf] + (uint32_t)(row * KPAD + col) * 2;
                asm volatile("ldmatrix.sync.aligned.m8n8.x4.shared.b16 "
                             "{%0,%1,%2,%3}, [%4];"
                             : "=r"(a[mf][0]), "=r"(a[mf][1]),
                               "=r"(a[mf][2]), "=r"(a[mf][3]) : "r"(addr));
            }
            uint32_t b[4][2];
            #pragma unroll
            for (int nf = 0; nf < 4; nf++) {
                const int row = wn * 32 + nf * 8 + (lane & 7);
                const int col = ks * 16 + ((lane >> 3) & 1) * 8;
                const uint32_t addr = sB[buf] + (uint32_t)(row * KPAD + col) * 2;
                asm volatile("ldmatrix.sync.aligned.m8n8.x2.shared.b16 "
                             "{%0,%1}, [%2];"
                             : "=r"(b[nf][0]), "=r"(b[nf][1]) : "r"(addr));
            }
            #pragma unroll
            for (int mf = 0; mf < 4; mf++)
                #pragma unroll
                for (int nf = 0; nf < 4; nf++)
                    asm volatile(
                        "mma.sync.aligned.m16n8k16.row.col.f32.bf16.bf16.f32 "
                        "{%0,%1,%2,%3}, {%4,%5,%6,%7}, {%8,%9}, {%0,%1,%2,%3};"
                        : "+f"(acc[mf][nf][0]), "+f"(acc[mf][nf][1]),
                          "+f"(acc[mf][nf][2]), "+f"(acc[mf][nf][3])
                        : "r"(a[mf][0]), "r"(a[mf][1]), "r"(a[mf][2]), "r"(a[mf][3]),
                          "r"(b[nf][0]), "r"(b[nf][1]));
        }
    }

    // epilogue: bf16x2 direct stores (n even, NT even => pair in-bounds check on n)
    #pragma unroll
    for (int mf = 0; mf < 4; mf++) {
        const int m = m0 + wm * 64 + mf * 16 + (lane >> 2);
        #pragma unroll
        for (int nf = 0; nf < 4; nf++) {
            const int n = n0 + wn * 32 + nf * 8 + (lane & 3) * 2;
            if (n < NT) {
                __nv_bfloat162 h0 = __float22bfloat162_rn(
                    make_float2(acc[mf][nf][0], acc[mf][nf][1]));
                __nv_bfloat162 h1 = __float22bfloat162_rn(
                    make_float2(acc[mf][nf][2], acc[mf][nf][3]));
                *(uint32_t*)(g_simh + (size_t)m * NT + n)       = *(uint32_t*)&h0;
                *(uint32_t*)(g_simh + (size_t)(m + 8) * NT + n) = *(uint32_t*)&h1;
            }
        }
    }
}

// ---------------------------------------------------------------------------
// Pass 2: per-row candidate select + exact rescore + topk + softmax + hist
// ---------------------------------------------------------------------------
#define NBINS 4096
#define HLO   (-256.0f)
#define HSC   8.0f
#define CAND  512
#define NTHR  256
#define MARGIN_BINS 8           // 1.0 sim units

__device__ __forceinline__ int bin_of(float v)
{
    int b = (int)((v - HLO) * HSC);
    return min(max(b, 0), NBINS - 1);
}

__global__ void __launch_bounds__(NTHR)
topk_kernel(const float* __restrict__ A, const float* __restrict__ B,
            const int* __restrict__ labels, float* __restrict__ out)
{
    const int row = blockIdx.x;
    const int tid = threadIdx.x;
    const uint4* simv = (const uint4*)(g_simh + (size_t)row * NT);   // 8 bf16 each

    __shared__ unsigned hist[NBINS];
    __shared__ int   cidx[CAND];
    __shared__ float cval[CAND];
    __shared__ unsigned long long ckey[CAND];
    __shared__ __align__(16) float arow[DIM];
    __shared__ float prob[NCLS];
    __shared__ float wgt[MAXK];
    __shared__ int   lab[MAXK];
    __shared__ float s_red[NTHR];
    __shared__ int   s_cnt, s_bstar;

    for (int i = tid; i < DIM; i += NTHR) arow[i] = A[(size_t)row * DIM + i];
    for (int b = tid; b < NBINS; b += NTHR) hist[b] = 0;
    if (tid == 0) s_cnt = 0;
    __syncthreads();

    // Phase 1: histogram of approx sims
    for (int i = tid; i < NT / 8; i += NTHR) {
        uint4 v = simv[i];
        const uint32_t w[4] = { v.x, v.y, v.z, v.w };
        #pragma unroll
        for (int q = 0; q < 4; q++) {
            __nv_bfloat162 h = *(const __nv_bfloat162*)&w[q];
            atomicAdd(&hist[bin_of(__bfloat162float(h.x))], 1u);
            atomicAdd(&hist[bin_of(__bfloat162float(h.y))], 1u);
        }
    }
    __syncthreads();

    // Phase 2: rank-200 bin
    if (tid == 0) {
        unsigned cum = 0; int b = NBINS - 1;
        while (b >= 0) { cum += hist[b]; if (cum >= MAXK) break; b--; }
        s_bstar = (b < 0) ? 0 : b;
    }
    __syncthreads();
    const int bstar = s_bstar;
    const int bthr  = max(bstar - MARGIN_BINS, 0);

    // Phase 3: collect candidates (margin below threshold for bf16 noise)
    for (int tier = 0; tier < 2; tier++) {
        for (int i = tid; i < NT / 8; i += NTHR) {
            uint4 v = simv[i];
            const uint32_t w[4] = { v.x, v.y, v.z, v.w };
            #pragma unroll
            for (int q = 0; q < 8; q++) {
                __nv_bfloat16 h = ((const __nv_bfloat16*)w)[q];
                const int b = bin_of(__bfloat162float(h));
                const bool take = tier ? (b >= bthr && b < bstar) : (b >= bstar);
                if (take) {
                    const int p = atomicAdd(&s_cnt, 1);
                    if (p < CAND) cidx[p] = i * 8 + q;
                }
            }
        }
        __syncthreads();
    }
    const int cnt = min(s_cnt, CAND);

    // Phase 4: exact fp32 rescore (one candidate per warp)
    const int lane = tid & 31, wrp = tid >> 5;
    const float4* a4 = (const float4*)arow;
    for (int c = wrp; c < cnt; c += 8) {
        const float4* b4 = (const float4*)(B + (size_t)cidx[c] * DIM);
        float acc = 0.f;
        #pragma unroll
        for (int j = 0; j < 8; j++) {
            const int k4 = j * 32 + lane;
            float4 bb = b4[k4], aa = a4[k4];
            acc = fmaf(aa.x, bb.x, acc); acc = fmaf(aa.y, bb.y, acc);
            acc = fmaf(aa.z, bb.z, acc); acc = fmaf(aa.w, bb.w, acc);
        }
        #pragma unroll
        for (int o = 16; o > 0; o >>= 1) acc += __shfl_down_sync(0xffffffffu, acc, o);
        if (lane == 0) cval[c] = acc;
    }
    __syncthreads();

    // Phase 5: sort keys (value desc, index asc — jax top_k order)
    for (int i = tid; i < CAND; i += NTHR) {
        if (i < cnt) {
            unsigned u = __float_as_uint(cval[i]);
            unsigned s = (u & 0x80000000u) ? ~u : (u | 0x80000000u);
            ckey[i] = ((unsigned long long)s << 32) | (unsigned)(~(unsigned)cidx[i]);
        } else ckey[i] = 0ull;
    }
    __syncthreads();

    for (int ksz = 2; ksz <= CAND; ksz <<= 1)
        for (int st = ksz >> 1; st > 0; st >>= 1) {
            for (int j = tid; j < CAND; j += NTHR) {
                const int ixj = j ^ st;
                if (ixj > j) {
                    const unsigned long long a = ckey[j], b = ckey[ixj];
                    const bool desc = ((j & ksz) == 0);
                    if (desc ? (a < b) : (a > b)) { ckey[j] = b; ckey[ixj] = a; }
                }
            }
            __syncthreads();
        }

    // Phase 6: softmax over top-200
    float maxv;
    {
        const unsigned s0 = (unsigned)(ckey[0] >> 32);
        const unsigned u0 = (s0 & 0x80000000u) ? (s0 & 0x7fffffffu) : ~s0;
        maxv = __uint_as_float(u0);
    }
    float wv = 0.f;
    if (tid < MAXK) {
        const unsigned long long k = ckey[tid];
        const unsigned s = (unsigned)(k >> 32);
        const unsigned u = (s & 0x80000000u) ? (s & 0x7fffffffu) : ~s;
        const float v = __uint_as_float(u);
        const int idx = (int)(~(unsigned)k);
        wv = expf((v - maxv) * TINV);
        wgt[tid] = wv;
        lab[tid] = labels[idx];
    }
    s_red[tid] = wv;
    __syncthreads();
    for (int off = NTHR / 2; off > 0; off >>= 1) {
        if (tid < off) s_red[tid] += s_red[tid + off];
        __syncthreads();
    }
    const float inv = 1.0f / s_red[0];

    // Phase 7: 4 prefix class-histograms
    const int KS[4] = { 10, 20, 100, 200 };
    #pragma unroll
    for (int kk = 0; kk < 4; kk++) {
        for (int c = tid; c < NCLS; c += NTHR) prob[c] = 0.f;
        __syncthreads();
        if (tid < KS[kk]) atomicAdd(&prob[lab[tid]], wgt[tid] * inv);
        __syncthreads();
        float* o = out + ((size_t)kk * NQ + row) * NCLS;
        for (int c = tid; c < NCLS; c += NTHR) o[c] = prob[c];
        __syncthreads();
    }
}

// ---------------------------------------------------------------------------
extern "C" void kernel_launch(void* const* d_in, const int* in_sizes, int n_in,
                              void* d_out, int out_size)
{
    const float* A      = (const float*)d_in[0];   // [2048,1024]
    const float* B      = (const float*)d_in[1];   // [100000,1024]
    const int*   labels = (const int*)d_in[2];     // [100000]
    float*       out    = (float*)d_out;           // 4 x [2048,1000]

    __nv_bfloat16 *bA, *bB;
    cudaGetSymbolAddress((void**)&bA, g_bA);
    cudaGetSymbolAddress((void**)&bB, g_bB);

    conv_bf16<<<(NQ * DIM / 8 + 255) / 256, 256>>>(A, bA, NQ * DIM / 8);
    conv_bf16<<<(NT * DIM / 8 + 255) / 256, 256>>>(B, bB, NT * DIM / 8);

    dim3 grid(NQ / BM, (NT + BN - 1) / BN);        // 16 x 782
    gemm_mma<<<grid, 256>>>(bA, bB);

    topk_kernel<<<NQ, NTHR>>>(A, B, labels, out);
}